// round 8
// baseline (speedup 1.0000x reference)
#include <cuda_runtime.h>
#include <cstdint>

#define HH 512
#define WW 512
#define CCH 3
#define SS 2
#define AA 3
#define NB 8
#define BB 2
#define SKS 9
#define AKS 7

__device__ float g_conv[CCH * SS * HH * WW];   // sigma-blurred maps

// ---------------------------------------------------------------------------
// Fused sigma blur: clip + separable 9-tap (both sigmas) per 32x32 tile.
// 1D weights (= row sums of the 2D kernel, exact rank-1) derived per CTA.
// ---------------------------------------------------------------------------
#define STW 32
#define STH 32
#define SIN 40

__global__ __launch_bounds__(256) void k_sigma(const float* __restrict__ im,
                                               const float* __restrict__ sig2d) {
    __shared__ float s_in[SIN][SIN];
    __shared__ float s_ht[SS][SIN][STW + 1];
    __shared__ float wsig[SS * 5];
    int tid = threadIdx.x;
    int c = blockIdx.z;
    int gy0 = blockIdx.y * STH, gx0 = blockIdx.x * STW;

    if (tid < SS * 5) {
        int s = tid / 5, k = tid % 5;
        float sum = 0.f;
        for (int j = 0; j < SKS; j++) sum += __ldg(&sig2d[(s * SKS + k) * SKS + j]);
        wsig[tid] = sum;
    }
    for (int i = tid; i < SIN * SIN; i += 256) {
        int r = i / SIN, q = i - r * SIN;
        int gy = gy0 + r - 4, gx = gx0 + q - 4;
        float v = 0.f;
        if (gy >= 0 && gy < HH && gx >= 0 && gx < WW) {
            v = __ldg(&im[((size_t)gy * WW + gx) * CCH + c]);
            v = fminf(fmaxf(v, 0.f), 1.f);
        }
        s_in[r][q] = v;
    }
    __syncthreads();
    float w[SS][5];
#pragma unroll
    for (int s = 0; s < SS; s++)
#pragma unroll
        for (int k = 0; k < 5; k++) w[s][k] = wsig[s * 5 + k];

    for (int i = tid; i < SIN * STW; i += 256) {
        int r = i / STW, x = i - r * STW;
        const float* row = &s_in[r][x];
        float p0 = row[0] + row[8], p1 = row[1] + row[7];
        float p2 = row[2] + row[6], p3 = row[3] + row[5];
        float m = row[4];
#pragma unroll
        for (int s = 0; s < SS; s++) {
            float acc = w[s][4] * m;
            acc = fmaf(w[s][0], p0, acc);
            acc = fmaf(w[s][1], p1, acc);
            acc = fmaf(w[s][2], p2, acc);
            acc = fmaf(w[s][3], p3, acc);
            s_ht[s][r][x] = acc;
        }
    }
    __syncthreads();

    for (int i = tid; i < STH * STW; i += 256) {
        int y = i / STW, x = i - y * STW;
#pragma unroll
        for (int s = 0; s < SS; s++) {
            const float* col = &s_ht[s][y][x];
            const int L = STW + 1;
            float p0 = col[0] + col[8 * L], p1 = col[1 * L] + col[7 * L];
            float p2 = col[2 * L] + col[6 * L], p3 = col[3 * L] + col[5 * L];
            float m = col[4 * L];
            float acc = w[s][4] * m;
            acc = fmaf(w[s][0], p0, acc);
            acc = fmaf(w[s][1], p1, acc);
            acc = fmaf(w[s][2], p2, acc);
            acc = fmaf(w[s][3], p3, acc);
            g_conv[(((size_t)c * SS + s) * HH + gy0 + y) * WW + gx0 + x] = acc;
        }
    }
}

// ---------------------------------------------------------------------------
// Packed f32x2 helpers
// ---------------------------------------------------------------------------
union F2U { float2 f; unsigned long long u; };
__device__ __forceinline__ float2 ffma2(float2 a, float2 b, float2 c) {
    F2U A, B, C, D; A.f = a; B.f = b; C.f = c;
    asm("fma.rn.f32x2 %0, %1, %2, %3;" : "=l"(D.u) : "l"(A.u), "l"(B.u), "l"(C.u));
    return D.f;
}
__device__ __forceinline__ float2 fmul2(float2 a, float2 b) {
    F2U A, B, D; A.f = a; B.f = b;
    asm("mul.rn.f32x2 %0, %1, %2;" : "=l"(D.u) : "l"(A.u), "l"(B.u));
    return D.f;
}
__device__ __forceinline__ float2 fadd2(float2 a, float2 b) {
    F2U A, B, D; A.f = a; B.f = b;
    asm("add.rn.f32x2 %0, %1, %2;" : "=l"(D.u) : "l"(A.u), "l"(B.u));
    return D.f;
}

// ---------------------------------------------------------------------------
// K2: thread = (x-pair, bin). iso stored scalar with x-stride 12 (bank-
// disjoint LDS.32 window: 8 loads serve 2 outputs). float2 lanes = (x, x+1).
// Alphas 0,1: register scatter rings. Alpha 2: thread-private smem ring.
// ---------------------------------------------------------------------------
#define W_T 64
#define H_T 32
#define RIN 38           // H_T + 6 input rows
#define POS 70           // W_T + 6 iso x positions per row
#define XS 12            // iso x stride (floats) -> conflict-free taps
#define ISO_SLAB (POS * XS)

struct SMemL {
    float  conv[RIN * POS];        // 10640 B
    float  iso[4 * ISO_SLAB];      // 13440 B, slab = row & 3
    float2 h2[7][256];             // 14336 B, alpha2 hconv ring
    float  wal[AA * 4];
};

__global__ __launch_bounds__(256, 3) void k_loi(const float* __restrict__ al2d,
                                                const float* __restrict__ centers,
                                                const float* __restrict__ betas,
                                                float* __restrict__ out) {
    __shared__ SMemL sm;
    int tid = threadIdx.x;
    int xp = tid >> 3, bin = tid & 7;        // xp: 0..31 (x pair), bin: 0..7
    int z = blockIdx.z;
    int c = z / SS, s = z % SS;
    int gy0 = blockIdx.y * H_T;
    int gx0 = blockIdx.x * W_T;
    const float* convmap = g_conv + (size_t)z * HH * WW;

    if (tid < AA * 4) {
        int a = tid >> 2, k = tid & 3;
        float sum = 0.f;
        for (int j = 0; j < AKS; j++) sum += __ldg(&al2d[(a * AKS + k) * AKS + j]);
        sm.wal[tid] = sum;
    }
    for (int i = tid; i < RIN * POS; i += 256) {
        int r = i / POS, q = i - r * POS;
        int gy = gy0 + r - 3, gx = gx0 + q - 3;
        sm.conv[i] = (gy >= 0 && gy < HH && gx >= 0 && gx < WW)
                     ? __ldg(&convmap[(size_t)gy * WW + gx]) : -1e30f;
    }
    float cn = __ldg(&centers[bin]);
    __syncthreads();

    float2 wk[AA][4];
#pragma unroll
    for (int a = 0; a < AA; a++)
#pragma unroll
        for (int k = 0; k < 4; k++) {
            float w = sm.wal[a * 4 + k];
            wk[a][k] = make_float2(w, w);
        }

    const size_t ASTRF = (size_t)BB * SS * CCH * HH * WW * NB;  // alpha stride

#pragma unroll 1
    for (int b = 0; b < BB; b++) {
        float invb = 1.f / __ldg(&betas[b]);
        float nrm = 0.3989422804014327f * invb;
        float kf = -0.5f * invb * invb;

        auto produce = [&](int R) {
            float* slab = &sm.iso[(R & 3) * ISO_SLAB];
            const float* crow = &sm.conv[R * POS];
#pragma unroll
            for (int rd = 0; rd < 3; rd++) {
                int xx = xp + rd * 32;
                if (rd < 2 || xx < POS) {
                    float d = crow[xx] - cn;
                    slab[xx * XS + bin] = nrm * __expf(kf * d * d);
                }
            }
        };

        produce(0); produce(1);
        __syncthreads();

        float2 acc[2][7];
        float* outB = out + (size_t)((b * SS + s) * CCH + c) * (HH * WW * NB);

#pragma unroll 1
        for (int r7 = 0; r7 < 6; r7++) {
#pragma unroll
            for (int rr = 0; rr < 7; rr++) {
                int row = r7 * 7 + rr;
                if (row < RIN) {
                    // ---- window: 8 scalar taps serve outputs x=2xp, 2xp+1 ----
                    const float* w8 = &sm.iso[(row & 3) * ISO_SLAB + (2 * xp) * XS + bin];
                    float v0 = w8[0],      v1 = w8[XS],     v2 = w8[2 * XS], v3 = w8[3 * XS];
                    float v4 = w8[4 * XS], v5 = w8[5 * XS], v6 = w8[6 * XS], v7 = w8[7 * XS];
                    float2 m01 = make_float2(v3, v4);
                    float2 s0 = make_float2(v0 + v6, v1 + v7);
                    float2 s1 = make_float2(v1 + v5, v2 + v6);
                    float2 s2 = make_float2(v2 + v4, v3 + v5);
                    float2 hv0 = fmul2(wk[0][3], m01);
                    float2 hv1 = fmul2(wk[1][3], m01);
                    float2 hv2 = fmul2(wk[2][3], m01);
                    hv0 = ffma2(wk[0][0], s0, hv0);
                    hv1 = ffma2(wk[1][0], s0, hv1);
                    hv2 = ffma2(wk[2][0], s0, hv2);
                    hv0 = ffma2(wk[0][1], s1, hv0);
                    hv1 = ffma2(wk[1][1], s1, hv1);
                    hv2 = ffma2(wk[2][1], s1, hv2);
                    hv0 = ffma2(wk[0][2], s2, hv0);
                    hv1 = ffma2(wk[1][2], s2, hv1);
                    hv2 = ffma2(wk[2][2], s2, hv2);

                    // alpha2: stash hconv in thread-private smem ring
                    sm.h2[rr][tid] = hv2;

                    // alphas 0,1: register scatter rings (unconditional;
                    // stale slots are re-initialized at t==0 before any store)
#pragma unroll
                    for (int t = 0; t < 7; t++) {
                        const int slot = ((rr - t) % 7 + 7) % 7;
                        const int wi = (t < 4) ? t : 6 - t;
                        if (t == 0) {
                            acc[0][slot] = fmul2(wk[0][wi], hv0);
                            acc[1][slot] = fmul2(wk[1][wi], hv1);
                        } else {
                            acc[0][slot] = ffma2(wk[0][wi], hv0, acc[0][slot]);
                            acc[1][slot] = ffma2(wk[1][wi], hv1, acc[1][slot]);
                        }
                    }

                    // ---- completed output row y = row - 6 ----
                    if (row >= 6) {
                        const int slot = (rr + 1) % 7;
                        float2 g0 = sm.h2[(rr + 1) % 7][tid];
                        float2 g1 = sm.h2[(rr + 2) % 7][tid];
                        float2 g2 = sm.h2[(rr + 3) % 7][tid];
                        float2 g3 = sm.h2[(rr + 4) % 7][tid];
                        float2 g4 = sm.h2[(rr + 5) % 7][tid];
                        float2 g5 = sm.h2[(rr + 6) % 7][tid];
                        float2 sA = fadd2(g0, hv2);
                        float2 sB = fadd2(g1, g5);
                        float2 sC = fadd2(g2, g4);
                        float2 o2 = fmul2(wk[2][3], g3);
                        o2 = ffma2(wk[2][0], sA, o2);
                        o2 = ffma2(wk[2][1], sB, o2);
                        o2 = ffma2(wk[2][2], sC, o2);

                        float2 r0 = acc[0][slot], r1 = acc[1][slot];
                        size_t off = ((size_t)(gy0 + row - 6) * WW + gx0 + 2 * xp) * NB + bin;
                        float* q = outB + off;
                        q[0] = r0.x;  q[NB] = r0.y;
                        q[ASTRF] = r1.x;  q[ASTRF + NB] = r1.y;
                        q[2 * ASTRF] = o2.x;  q[2 * ASTRF + NB] = o2.y;
                    }

                    // ---- pipelined iso production (next 2 rows) ----
                    if ((row & 1) == 1) {
                        if (row + 1 < RIN) produce(row + 1);
                        if (row + 2 < RIN) produce(row + 2);
                    }
                }
                if (((r7 * 7 + rr) & 1) == 1) __syncthreads();
            }
        }
    }
}

// ---------------------------------------------------------------------------
extern "C" void kernel_launch(void* const* d_in, const int* in_sizes, int n_in,
                              void* d_out, int out_size) {
    const float* im      = (const float*)d_in[0];   // (512,512,3)
    const float* sig2d   = (const float*)d_in[1];   // (2,9,9)
    const float* al2d    = (const float*)d_in[2];   // (3,7,7)
    const float* centers = (const float*)d_in[3];   // (8,)
    const float* betas   = (const float*)d_in[4];   // (2,)
    float* out = (float*)d_out;

    dim3 gs(WW / STW, HH / STH, CCH);
    k_sigma<<<gs, 256>>>(im, sig2d);
    dim3 g(WW / W_T, HH / H_T, CCH * SS);
    k_loi<<<g, 256>>>(al2d, centers, betas, out);
}